// round 15
// baseline (speedup 1.0000x reference)
#include <cuda_runtime.h>
#include <cuda_fp16.h>
#include <cooperative_groups.h>

namespace cg = cooperative_groups;

// ---------------------------------------------------------------------------
// ConvDiffLogicMNIST — difflogic CNN forward, ONE cooperative kernel.
// Gate algebra: out = A + B*a + C*b + D*a*b (per-gate coefs from softmax(w)).
// R14: phase 1 (all 37k gate softmaxes over the whole grid + wiring decode)
//      -> grid.sync() -> phase 2 (per-image network, R13 mega body).
// ---------------------------------------------------------------------------

#define DEV_INLINE __device__ __forceinline__

static constexpr int NT = 1024;   // threads per block

// ---- conv coefficient table offsets (float4 units) ----
static constexpr int OFF_C1_0 = 0;       // 16*4
static constexpr int OFF_C1_1 = 64;      // 16*2
static constexpr int OFF_C1_2 = 96;      // 16*1
static constexpr int OFF_C2_0 = 112;     // 48*4
static constexpr int OFF_C2_1 = 304;     // 48*2
static constexpr int OFF_C2_2 = 400;     // 48*1
static constexpr int OFF_C3_0 = 448;     // 144*4
static constexpr int OFF_C3_1 = 1024;    // 144*2
static constexpr int OFF_C3_2 = 1312;    // 144*1
static constexpr int N_CONV_COEF = 1456;

// ---- fc gate offsets (gate units; all even so pairs never straddle) ----
static constexpr int FC1_OFF = 0;        // 20480
static constexpr int FC2_OFF = 20480;    // 10240
static constexpr int FC3_OFF = 30720;    // 5120
static constexpr int N_FC    = 35840;
static constexpr int N_GATES = 37296;

// ---- smem layout (float units) ----
static constexpr int S_LUT   = 0;                    // 16*256 = 4096
static constexpr int S_XBIN  = 4096;                 // 784 (int)
static constexpr int S_ACT1  = 4880;                 // 16*14*14 = 3136 (padded, f32)
static constexpr int S_ACT2  = 8016;                 // 48*8*8  = 3072 (padded, f32)
static constexpr int S_ACT3h = 11088;                // 1296 half = 648 fl
static constexpr int S_FC1h  = 11736;                // 20480 half = 10240 fl (fc3 reuses)
static constexpr int S_FC2h  = 21976;                // 10240 half = 5120 fl
static constexpr int S_WIRE  = 27096;                // 144*9 (int)
static constexpr int SMEM_BYTES = (S_WIRE + 144 * 9) * 4;   // ~113.6 KB

// ---- device scratch ----
__device__ float4 g_coef[N_CONV_COEF];
__device__ uint2  g_fci2[N_FC / 2];   // per pair: (ia0|ib0<<16, ia1|ib1<<16)
__device__ uint4  g_fcc4[N_FC / 2];   // per pair: half2 A01,B01,C01,D01
__device__ int    g_sel1[16];         // conv1 per-filter selector bits
__device__ int    g_wire1[128];       // conv1 taps (16 filters x 8)
__device__ int    g_wire2[48 * 9];    // conv2 decoded wiring
__device__ int    g_wire3[144 * 9];   // conv3 decoded wiring

// op -> (const, a, b, ab) coefficients for the 16 two-input soft boolean ops
__constant__ float OPC0[16]  = {0,0,0,0, 0,0,0,0, 1,1,1,1, 1,1,1,1};
__constant__ float OPCA[16]  = {0,0,1,1, 0,0,1,1, -1,-1,0,0, -1,-1,0,0};
__constant__ float OPCB[16]  = {0,0,0,0, 1,1,1,1, -1,-1,-1,-1, 0,0,0,0};
__constant__ float OPCAB[16] = {0,1,-1,0, -1,0,-2,-1, 1,2,0,1, 0,1,-1,0};

DEV_INLINE float gate_eval(float A, float Bc, float Cc, float D, float a, float b) {
    return fmaf(b, fmaf(a, D, Cc), fmaf(a, Bc, A));
}
DEV_INLINE float gate_eval4(float4 c, float a, float b) {
    return gate_eval(c.x, c.y, c.z, c.w, a, b);
}
DEV_INLINE float sel4(const float h[4], int i) {
    float r = h[0];
    r = (i == 1) ? h[1] : r;
    r = (i == 2) ? h[2] : r;
    r = (i == 3) ? h[3] : r;
    return r;
}

// array-free softmax -> bilinear coefs (accumulate unnormalized, scale once)
DEV_INLINE float4 softmax_coef(const float* __restrict__ w) {
    float m = -1e30f;
#pragma unroll
    for (int k = 0; k < 16; k++) m = fmaxf(m, w[k]);
    float sum = 0.f, A = 0.f, Bc = 0.f, Cc = 0.f, D = 0.f;
#pragma unroll
    for (int k = 0; k < 16; k++) {
        float p = __expf(w[k] - m);
        sum += p;
        A  = fmaf(p, OPC0[k],  A);
        Bc = fmaf(p, OPCA[k],  Bc);
        Cc = fmaf(p, OPCB[k],  Cc);
        D  = fmaf(p, OPCAB[k], D);
    }
    float inv = 1.f / sum;
    return make_float4(A * inv, Bc * inv, Cc * inv, D * inv);
}

DEV_INLINE void decode_wire(int f, int F, int INW, int KS,
                            const int* idx0, const int* idx1, const int* idx2,
                            int* wire) {
    int KSQ = KS * KS;
    int sel = 0;
#pragma unroll
    for (int g = 0; g < 2; g++) {
        sel |= (idx1[f * 2 + g] & 3) << (g * 2);
        sel |= (idx1[F * 2 + f * 2 + g] & 3) << (4 + g * 2);
    }
    sel |= (idx2[f] & 1) << 8;
    sel |= (idx2[F + f] & 1) << 9;
    wire[f * 9 + 8] = sel;
#pragma unroll
    for (int j = 0; j < 8; j++) {
        int p = (j < 4) ? idx0[f * 4 + j] : idx0[F * 4 + f * 4 + (j - 4)];
        int c = p / KSQ;
        int kk = p % KSQ;
        wire[f * 9 + j] = c * INW * INW + (kk / KS) * INW + (kk % KS);
    }
}

// ---------------------------------------------------------------------------
// Conv phase (conv2/conv3): padded smem in -> out (f32 or half), 2x2 maxpool.
// ---------------------------------------------------------------------------
template <int INW, int OH, int OUTW, int OUTB, int F, int OFF, bool OUTH>
DEV_INLINE void conv_phase(const float* __restrict__ in_s, void* __restrict__ out_p,
                           const int* __restrict__ gwire, int* __restrict__ wire,
                           int tid) {
    constexpr int OHP = OH / 2;
    constexpr int NOUT = F * OHP * OHP;

    for (int i = tid; i < F * 9; i += NT) wire[i] = gwire[i];
    __syncthreads();

    for (int o = tid; o < NOUT; o += NT) {
        int px = o % OHP;
        int py = (o / OHP) % OHP;
        int f  = o / (OHP * OHP);

        int toff[8];
#pragma unroll
        for (int j = 0; j < 8; j++) toff[j] = wire[f * 9 + j];
        int sel = wire[f * 9 + 8];

        float4 c0[4], c1[2], c2;
#pragma unroll
        for (int g = 0; g < 4; g++) c0[g] = g_coef[OFF + f * 4 + g];
#pragma unroll
        for (int g = 0; g < 2; g++) c1[g] = g_coef[OFF + F * 4 + f * 2 + g];
        c2 = g_coef[OFF + F * 6 + f];

        float m = -1e30f;
#pragma unroll
        for (int dy = 0; dy < 2; dy++) {
#pragma unroll
            for (int dx = 0; dx < 2; dx++) {
                int base = (2 * py + dy) * INW + (2 * px + dx);
                float v[8];
#pragma unroll
                for (int j = 0; j < 8; j++) v[j] = in_s[toff[j] + base];
                float h0[4];
#pragma unroll
                for (int g = 0; g < 4; g++) h0[g] = gate_eval4(c0[g], v[g], v[g + 4]);
                float h1[2];
                h1[0] = gate_eval4(c1[0], sel4(h0, sel & 3), sel4(h0, (sel >> 4) & 3));
                h1[1] = gate_eval4(c1[1], sel4(h0, (sel >> 2) & 3), sel4(h0, (sel >> 6) & 3));
                float ha = ((sel >> 8) & 1) ? h1[1] : h1[0];
                float hb = ((sel >> 9) & 1) ? h1[1] : h1[0];
                m = fmaxf(m, gate_eval4(c2, ha, hb));
            }
        }
        int oi = f * OUTW * OUTW + (py + OUTB) * OUTW + (px + OUTB);
        if (OUTH)
            reinterpret_cast<__half*>(out_p)[oi] = __float2half(m);
        else
            reinterpret_cast<float*>(out_p)[oi] = m;
    }
    __syncthreads();
}

// ---------------------------------------------------------------------------
// FC phase (half2, 2 gates per step): smem half in -> smem half out.
// ---------------------------------------------------------------------------
template <int DOUT, int GOFF>
DEV_INLINE void fc_phase_h(const __half* __restrict__ in_s, __half* __restrict__ out_s,
                           int tid) {
    constexpr int PAIRS = DOUT / 2;
    constexpr int POFF = GOFF / 2;
#pragma unroll 4
    for (int p = tid; p < PAIRS; p += NT) {
        uint2 ri = __ldg(&g_fci2[POFF + p]);
        uint4 rc = __ldg(&g_fcc4[POFF + p]);
        __half a0 = in_s[ri.x & 0xffffu], b0 = in_s[ri.x >> 16];
        __half a1 = in_s[ri.y & 0xffffu], b1 = in_s[ri.y >> 16];
        __half2 a01 = __halves2half2(a0, a1);
        __half2 b01 = __halves2half2(b0, b1);
        __half2 A2 = *reinterpret_cast<__half2*>(&rc.x);
        __half2 B2 = *reinterpret_cast<__half2*>(&rc.y);
        __half2 C2 = *reinterpret_cast<__half2*>(&rc.z);
        __half2 D2 = *reinterpret_cast<__half2*>(&rc.w);
        __half2 o01 = __hfma2(b01, __hfma2(a01, D2, C2), __hfma2(a01, B2, A2));
        reinterpret_cast<__half2*>(out_s)[p] = o01;
    }
    __syncthreads();
}

// ---------------------------------------------------------------------------
// The cooperative mega kernel: phase 1 (metadata) -> grid.sync -> phase 2.
// ---------------------------------------------------------------------------
struct CoefSeg { const float* w; const int* idx; int off; int cnt; };
struct CoefArgs { CoefSeg s[12]; };

__global__ __launch_bounds__(NT, 1)
void mega_kernel(const float* __restrict__ x, CoefArgs args, float* __restrict__ out) {
    extern __shared__ float sm[];
    int* xbin = reinterpret_cast<int*>(sm + S_XBIN);
    int* wire = reinterpret_cast<int*>(sm + S_WIRE);
    float* lut = sm + S_LUT;
    __half* act3h = reinterpret_cast<__half*>(sm + S_ACT3h);
    __half* fc1h  = reinterpret_cast<__half*>(sm + S_FC1h);
    __half* fc2h  = reinterpret_cast<__half*>(sm + S_FC2h);
    const int tid = threadIdx.x;
    const int b = blockIdx.x;
    const int gtid = b * NT + tid;
    const int gstride = gridDim.x * NT;

    // ---- per-image prologue (coef-independent) ----
    for (int i = tid; i < 3136; i += NT) sm[S_ACT1 + i] = 0.f;
    for (int i = tid; i < 3072; i += NT) sm[S_ACT2 + i] = 0.f;
    if (tid < 784)
        xbin[tid] = (x[b * 784 + tid] > 0.5f) ? 1 : 0;

    // ---- phase 1: all gate softmaxes across the whole grid ----
    for (int g = gtid; g < N_GATES; g += gstride) {
        int rem = g, i = 0;
        while (rem >= args.s[i].cnt) { rem -= args.s[i].cnt; i++; }
        float4 c = softmax_coef(args.s[i].w + rem * 16);
        if (i < 9) {
            g_coef[args.s[i].off + rem] = c;
        } else {
            int o = args.s[i].off + rem;
            int p = o >> 1, s = o & 1;
            const int* idx = args.s[i].idx;
            unsigned ia = (unsigned)idx[rem];
            unsigned ib = (unsigned)idx[args.s[i].cnt + rem];
            reinterpret_cast<unsigned*>(g_fci2)[p * 2 + s] = ia | (ib << 16);
            __half* ch = reinterpret_cast<__half*>(g_fcc4);
            ch[p * 8 + 0 + s] = __float2half(c.x);
            ch[p * 8 + 2 + s] = __float2half(c.y);
            ch[p * 8 + 4 + s] = __float2half(c.z);
            ch[p * 8 + 6 + s] = __float2half(c.w);
        }
    }

    // ---- phase 1b: wiring decode (block 0, high threads) ----
    if (b == 0 && tid >= 816) {
        int wt = tid - 816;
        if (wt < 48) {
            decode_wire(wt, 48, 14, 3, args.s[3].idx, args.s[4].idx, args.s[5].idx,
                        g_wire2);
        } else if (wt < 192) {
            decode_wire(wt - 48, 144, 8, 3, args.s[6].idx, args.s[7].idx,
                        args.s[8].idx, g_wire3);
        } else if (wt < 208) {
            int f = wt - 192;
            const int* idx0 = args.s[0].idx;   // c1_idx0
#pragma unroll
            for (int j = 0; j < 8; j++) {
                int p = (j < 4) ? idx0[f * 4 + j] : idx0[64 + f * 4 + (j - 4)];
                int kk = p % 25;
                g_wire1[f * 8 + j] = (p / 25) * 784 + (kk / 5) * 28 + (kk % 5);
            }
            // conv1 selector bits (same layout as conv_phase sel)
            const int* i1 = args.s[1].idx;
            const int* i2 = args.s[2].idx;
            int sel = 0;
#pragma unroll
            for (int g = 0; g < 2; g++) {
                sel |= (i1[f * 2 + g] & 3) << (g * 2);
                sel |= (i1[32 + f * 2 + g] & 3) << (4 + g * 2);
            }
            sel |= (i2[f] & 1) << 8;
            sel |= (i2[16 + f] & 1) << 9;
            g_sel1[f] = sel;
        }
    }

    // ---- grid-wide sync: all metadata visible ----
    cg::this_grid().sync();

    // ---- conv1 LUT: built per block from g_coef (L1-resident) ----
    if (tid < 128) wire[tid] = g_wire1[tid];
    for (int e = tid; e < 4096; e += NT) {
        int f = e >> 8, pat = e & 255;
        float4 c0[4];
#pragma unroll
        for (int g = 0; g < 4; g++) c0[g] = g_coef[OFF_C1_0 + f * 4 + g];
        int sel = g_sel1[f];
        float v[8];
#pragma unroll
        for (int j = 0; j < 8; j++) v[j] = (float)((pat >> j) & 1);
        float h0[4];
#pragma unroll
        for (int g = 0; g < 4; g++) h0[g] = gate_eval4(c0[g], v[g], v[g + 4]);
        float h1[2];
        h1[0] = gate_eval4(g_coef[OFF_C1_1 + f * 2],
                           sel4(h0, sel & 3), sel4(h0, (sel >> 4) & 3));
        h1[1] = gate_eval4(g_coef[OFF_C1_1 + f * 2 + 1],
                           sel4(h0, (sel >> 2) & 3), sel4(h0, (sel >> 6) & 3));
        float ha = ((sel >> 8) & 1) ? h1[1] : h1[0];
        float hb = ((sel >> 9) & 1) ? h1[1] : h1[0];
        lut[e] = gate_eval4(g_coef[OFF_C1_2 + f], ha, hb);
    }
    __syncthreads();

    // ---- conv1 via LUT + 2x2 pool -> act1 padded (16x14x14, f32) ----
    for (int o = tid; o < 2304; o += NT) {
        int px = o % 12;
        int py = (o / 12) % 12;
        int f  = o / 144;
        int toff[8];
#pragma unroll
        for (int j = 0; j < 8; j++) toff[j] = wire[f * 8 + j];
        const float* lf = lut + f * 256;
        float m = -1e30f;
#pragma unroll
        for (int dy = 0; dy < 2; dy++) {
#pragma unroll
            for (int dx = 0; dx < 2; dx++) {
                int base = (2 * py + dy) * 28 + (2 * px + dx);
                int pat = 0;
#pragma unroll
                for (int j = 0; j < 8; j++) pat |= xbin[toff[j] + base] << j;
                m = fmaxf(m, lf[pat]);
            }
        }
        sm[S_ACT1 + f * 196 + (py + 1) * 14 + (px + 1)] = m;
    }
    __syncthreads();

    // ---- conv2: act1 (14x14 padded) -> act2 padded (48x8x8, f32) ----
    conv_phase<14, 12, 8, 1, 48, OFF_C2_0, false>(
        sm + S_ACT1, sm + S_ACT2, g_wire2, wire, tid);
    // ---- conv3: act2 (8x8 padded) -> act3 (144x3x3, half) ----
    conv_phase<8, 6, 3, 0, 144, OFF_C3_0, true>(
        sm + S_ACT2, act3h, g_wire3, wire, tid);

    // ---- fc stack (half2 packed) ----
    fc_phase_h<20480, FC1_OFF>(act3h, fc1h, tid);
    fc_phase_h<10240, FC2_OFF>(fc1h, fc2h, tid);
    fc_phase_h<5120, FC3_OFF>(fc2h, fc1h, tid);   // fc3 out reuses fc1 buf

    // ---- groupsum: 10 classes x 512 gates (256 half2), one warp per class ----
    const __half2* f3 = reinterpret_cast<const __half2*>(fc1h);
    int w = tid >> 5, lane = tid & 31;
    if (w < 10) {
        float s = 0.f;
#pragma unroll
        for (int k = 0; k < 8; k++) {
            float2 t = __half22float2(f3[w * 256 + lane + 32 * k]);
            s += t.x + t.y;
        }
#pragma unroll
        for (int o = 16; o; o >>= 1) s += __shfl_xor_sync(0xffffffffu, s, o);
        if (lane == 0) out[b * 10 + w] = s * (1.f / 30.f);
    }
}

// ---------------------------------------------------------------------------
extern "C" void kernel_launch(void* const* d_in, const int* in_sizes, int n_in,
                              void* d_out, int out_size) {
    const float* x = (const float*)d_in[0];
    const int B = in_sizes[0] / (28 * 28);

    const int* c1_i0 = (const int*)d_in[1];
    const float* c1_w0 = (const float*)d_in[2];
    const int* c1_i1 = (const int*)d_in[3];
    const float* c1_w1 = (const float*)d_in[4];
    const int* c1_i2 = (const int*)d_in[5];
    const float* c1_w2 = (const float*)d_in[6];
    const int* c2_i0 = (const int*)d_in[7];
    const float* c2_w0 = (const float*)d_in[8];
    const int* c2_i1 = (const int*)d_in[9];
    const float* c2_w1 = (const float*)d_in[10];
    const int* c2_i2 = (const int*)d_in[11];
    const float* c2_w2 = (const float*)d_in[12];
    const int* c3_i0 = (const int*)d_in[13];
    const float* c3_w0 = (const float*)d_in[14];
    const int* c3_i1 = (const int*)d_in[15];
    const float* c3_w1 = (const float*)d_in[16];
    const int* c3_i2 = (const int*)d_in[17];
    const float* c3_w2 = (const float*)d_in[18];
    const int* fc1_i = (const int*)d_in[19];
    const float* fc1_w = (const float*)d_in[20];
    const int* fc2_i = (const int*)d_in[21];
    const float* fc2_w = (const float*)d_in[22];
    const int* fc3_i = (const int*)d_in[23];
    const float* fc3_w = (const float*)d_in[24];
    float* out = (float*)d_out;

    CoefArgs ca;
    ca.s[0]  = {c1_w0, c1_i0, OFF_C1_0, 64};
    ca.s[1]  = {c1_w1, c1_i1, OFF_C1_1, 32};
    ca.s[2]  = {c1_w2, c1_i2, OFF_C1_2, 16};
    ca.s[3]  = {c2_w0, c2_i0, OFF_C2_0, 192};
    ca.s[4]  = {c2_w1, c2_i1, OFF_C2_1, 96};
    ca.s[5]  = {c2_w2, c2_i2, OFF_C2_2, 48};
    ca.s[6]  = {c3_w0, c3_i0, OFF_C3_0, 576};
    ca.s[7]  = {c3_w1, c3_i1, OFF_C3_1, 288};
    ca.s[8]  = {c3_w2, c3_i2, OFF_C3_2, 144};
    ca.s[9]  = {fc1_w, fc1_i, FC1_OFF, 20480};
    ca.s[10] = {fc2_w, fc2_i, FC2_OFF, 10240};
    ca.s[11] = {fc3_w, fc3_i, FC3_OFF, 5120};

    cudaFuncSetAttribute(mega_kernel, cudaFuncAttributeMaxDynamicSharedMemorySize,
                         SMEM_BYTES);

    void* kargs[3] = {(void*)&x, (void*)&ca, (void*)&out};
    cudaLaunchCooperativeKernel((void*)mega_kernel, dim3(B, 1, 1), dim3(NT, 1, 1),
                                kargs, SMEM_BYTES, 0);
}

// round 16
// speedup vs baseline: 1.4759x; 1.4759x over previous
#include <cuda_runtime.h>
#include <cuda_fp16.h>

// ---------------------------------------------------------------------------
// ConvDiffLogicMNIST — difflogic CNN forward, fully fused mega kernel.
// Gate algebra: out = A + B*a + C*b + D*a*b (per-gate coefs from softmax(w)).
// R16: R13 shell (coef kernel + PDL mega) + two stall fixes inside mega:
//      (1) fc metadata one-ahead prefetch rotation, (2) conv coefs staged
//      into the dead LUT smem region (LDS instead of scattered LDG).
// ---------------------------------------------------------------------------

#define DEV_INLINE __device__ __forceinline__

static constexpr int NT = 1024;   // threads per mega block

// ---- conv coefficient table offsets (float4 units) ----
static constexpr int OFF_C1_0 = 0;       // 16*4
static constexpr int OFF_C1_1 = 64;      // 16*2
static constexpr int OFF_C1_2 = 96;      // 16*1
static constexpr int OFF_C2_0 = 112;     // 48*4
static constexpr int OFF_C3_0 = 448;     // 144*4
static constexpr int N_CONV_COEF = 1456;

// ---- fc gate offsets (gate units; all even so pairs never straddle) ----
static constexpr int FC1_OFF = 0;        // 20480
static constexpr int FC2_OFF = 20480;    // 10240
static constexpr int FC3_OFF = 30720;    // 5120
static constexpr int N_FC    = 35840;
static constexpr int N_GATES = 37296;

// ---- smem layout (float units) ----
static constexpr int S_LUT   = 0;                    // 4096 (LUT, then conv coefs)
static constexpr int S_XBIN  = 4096;                 // 784 (int)
static constexpr int S_ACT1  = 4880;                 // 16*14*14 = 3136 (padded, f32)
static constexpr int S_ACT2  = 8016;                 // 48*8*8  = 3072 (padded, f32)
static constexpr int S_ACT3h = 11088;                // 1296 half = 648 fl
static constexpr int S_FC1h  = 11736;                // 20480 half = 10240 fl
static constexpr int S_FC2h  = 21976;                // 10240 half = 5120 fl
static constexpr int S_WIRE  = 27096;                // 144*9 (int)
static constexpr int SMEM_BYTES = (S_WIRE + 144 * 9) * 4;   // ~113.6 KB

// ---- device scratch ----
__device__ float4 g_coef[N_CONV_COEF];
__device__ uint2  g_fci2[N_FC / 2];   // per pair: (ia0|ib0<<16, ia1|ib1<<16)
__device__ uint4  g_fcc4[N_FC / 2];   // per pair: half2 A01,B01,C01,D01
__device__ float  g_lut[4096];        // conv1 16x256 LUT
__device__ int    g_wire1[128];       // conv1 taps (16 filters x 8)
__device__ int    g_wire2[48 * 9];    // conv2 decoded wiring
__device__ int    g_wire3[144 * 9];   // conv3 decoded wiring

// op -> (const, a, b, ab) coefficients for the 16 two-input soft boolean ops
__constant__ float OPC0[16]  = {0,0,0,0, 0,0,0,0, 1,1,1,1, 1,1,1,1};
__constant__ float OPCA[16]  = {0,0,1,1, 0,0,1,1, -1,-1,0,0, -1,-1,0,0};
__constant__ float OPCB[16]  = {0,0,0,0, 1,1,1,1, -1,-1,-1,-1, 0,0,0,0};
__constant__ float OPCAB[16] = {0,1,-1,0, -1,0,-2,-1, 1,2,0,1, 0,1,-1,0};

DEV_INLINE float gate_eval(float A, float Bc, float Cc, float D, float a, float b) {
    return fmaf(b, fmaf(a, D, Cc), fmaf(a, Bc, A));
}
DEV_INLINE float gate_eval4(float4 c, float a, float b) {
    return gate_eval(c.x, c.y, c.z, c.w, a, b);
}
DEV_INLINE float sel4(const float h[4], int i) {
    float r = h[0];
    r = (i == 1) ? h[1] : r;
    r = (i == 2) ? h[2] : r;
    r = (i == 3) ? h[3] : r;
    return r;
}

DEV_INLINE void decode_wire(int f, int F, int INW, int KS,
                            const int* idx0, const int* idx1, const int* idx2,
                            int* wire) {
    int KSQ = KS * KS;
    int sel = 0;
#pragma unroll
    for (int g = 0; g < 2; g++) {
        sel |= (idx1[f * 2 + g] & 3) << (g * 2);
        sel |= (idx1[F * 2 + f * 2 + g] & 3) << (4 + g * 2);
    }
    sel |= (idx2[f] & 1) << 8;
    sel |= (idx2[F + f] & 1) << 9;
    wire[f * 9 + 8] = sel;
#pragma unroll
    for (int j = 0; j < 8; j++) {
        int p = (j < 4) ? idx0[f * 4 + j] : idx0[F * 4 + f * 4 + (j - 4)];
        int c = p / KSQ;
        int kk = p % KSQ;
        wire[f * 9 + j] = c * INW * INW + (kk / KS) * INW + (kk % KS);
    }
}

// ---------------------------------------------------------------------------
// Kernel 1 (primary): softmax(w) -> coefs; fc -> pair-packed half metadata.
// Block 0 additionally builds the conv1 LUT; block 1 decodes conv wiring.
// ---------------------------------------------------------------------------
struct CoefSeg { const float* w; const int* idx; int off; int cnt; };
struct CoefArgs { CoefSeg s[12]; };

__global__ void coef_kernel(CoefArgs args) {
    __shared__ float4 sc[112];   // conv1 gate coefs (block 0 only)
    int tid = threadIdx.x;
    int gid = blockIdx.x * 256 + tid;

    if (gid < N_GATES) {
        int rem = gid, i = 0;
        while (rem >= args.s[i].cnt) { rem -= args.s[i].cnt; i++; }
        const float* w = args.s[i].w + rem * 16;

        float wv[16], m = -1e30f;
#pragma unroll
        for (int k = 0; k < 16; k++) { wv[k] = w[k]; m = fmaxf(m, wv[k]); }
        float e[16], sum = 0.f;
#pragma unroll
        for (int k = 0; k < 16; k++) { e[k] = __expf(wv[k] - m); sum += e[k]; }
        float inv = 1.f / sum;
        float A = 0.f, Bc = 0.f, Cc = 0.f, D = 0.f;
#pragma unroll
        for (int k = 0; k < 16; k++) {
            float p = e[k] * inv;
            A  = fmaf(p, OPC0[k],  A);
            Bc = fmaf(p, OPCA[k],  Bc);
            Cc = fmaf(p, OPCB[k],  Cc);
            D  = fmaf(p, OPCAB[k], D);
        }
        if (i < 9) {
            g_coef[args.s[i].off + rem] = make_float4(A, Bc, Cc, D);
            if (blockIdx.x == 0 && gid < 112)
                sc[gid] = make_float4(A, Bc, Cc, D);
        } else {
            int o = args.s[i].off + rem;     // global fc gate id
            int p = o >> 1, s = o & 1;
            const int* idx = args.s[i].idx;
            unsigned ia = (unsigned)idx[rem];
            unsigned ib = (unsigned)idx[args.s[i].cnt + rem];
            reinterpret_cast<unsigned*>(g_fci2)[p * 2 + s] = ia | (ib << 16);
            __half* ch = reinterpret_cast<__half*>(g_fcc4);
            ch[p * 8 + 0 + s] = __float2half(A);
            ch[p * 8 + 2 + s] = __float2half(Bc);
            ch[p * 8 + 4 + s] = __float2half(Cc);
            ch[p * 8 + 6 + s] = __float2half(D);
        }
    }

    if (blockIdx.x == 0) {
        __syncthreads();
        const int* i1 = args.s[1].idx;   // c1_idx1
        const int* i2 = args.s[2].idx;   // c1_idx2
        for (int e = tid; e < 4096; e += 256) {
            int f = e >> 8, pat = e & 255;
            float v[8];
#pragma unroll
            for (int j = 0; j < 8; j++) v[j] = (float)((pat >> j) & 1);
            float h0[4];
#pragma unroll
            for (int g = 0; g < 4; g++)
                h0[g] = gate_eval4(sc[f * 4 + g], v[g], v[g + 4]);
            float h1[2];
            h1[0] = gate_eval4(sc[64 + f * 2],
                               sel4(h0, i1[f * 2] & 3), sel4(h0, i1[32 + f * 2] & 3));
            h1[1] = gate_eval4(sc[64 + f * 2 + 1],
                               sel4(h0, i1[f * 2 + 1] & 3), sel4(h0, i1[32 + f * 2 + 1] & 3));
            float ha = (i2[f] & 1) ? h1[1] : h1[0];
            float hb = (i2[16 + f] & 1) ? h1[1] : h1[0];
            g_lut[e] = gate_eval4(sc[96 + f], ha, hb);
        }
    } else if (blockIdx.x == 1) {
        if (tid < 48)
            decode_wire(tid, 48, 14, 3, args.s[3].idx, args.s[4].idx, args.s[5].idx,
                        g_wire2);
        else if (tid < 192)
            decode_wire(tid - 48, 144, 8, 3, args.s[6].idx, args.s[7].idx,
                        args.s[8].idx, g_wire3);
        else if (tid < 208) {
            int f = tid - 192;
            const int* idx0 = args.s[0].idx;   // c1_idx0
#pragma unroll
            for (int j = 0; j < 8; j++) {
                int p = (j < 4) ? idx0[f * 4 + j] : idx0[64 + f * 4 + (j - 4)];
                int kk = p % 25;
                g_wire1[f * 8 + j] = (p / 25) * 784 + (kk / 5) * 28 + (kk % 5);
            }
        }
    }
}

// ---------------------------------------------------------------------------
// Conv phase (conv2/conv3): padded smem in -> out (f32 or half), 2x2 maxpool.
// Wiring copied to smem; coefs staged into the (dead) LUT smem region so the
// hot loop reads coefs via LDS, not scattered LDG.
// ---------------------------------------------------------------------------
template <int INW, int OH, int OUTW, int OUTB, int F, int GOFF, bool OUTH>
DEV_INLINE void conv_phase(const float* __restrict__ in_s, void* __restrict__ out_p,
                           const int* __restrict__ gwire, int* __restrict__ wire,
                           float4* __restrict__ scf, int tid) {
    constexpr int OHP = OH / 2;
    constexpr int NOUT = F * OHP * OHP;
    constexpr int NCF = F * 7;   // float4 records for this layer (c0 x4,c1 x2,c2)

    for (int i = tid; i < F * 9; i += NT) wire[i] = gwire[i];
    for (int i = tid; i < NCF; i += NT) scf[i] = g_coef[GOFF + i];
    __syncthreads();

    for (int o = tid; o < NOUT; o += NT) {
        int px = o % OHP;
        int py = (o / OHP) % OHP;
        int f  = o / (OHP * OHP);

        int toff[8];
#pragma unroll
        for (int j = 0; j < 8; j++) toff[j] = wire[f * 9 + j];
        int sel = wire[f * 9 + 8];

        float4 c0[4], c1[2], c2;
#pragma unroll
        for (int g = 0; g < 4; g++) c0[g] = scf[f * 4 + g];
#pragma unroll
        for (int g = 0; g < 2; g++) c1[g] = scf[F * 4 + f * 2 + g];
        c2 = scf[F * 6 + f];

        float m = -1e30f;
#pragma unroll
        for (int dy = 0; dy < 2; dy++) {
#pragma unroll
            for (int dx = 0; dx < 2; dx++) {
                int base = (2 * py + dy) * INW + (2 * px + dx);
                float v[8];
#pragma unroll
                for (int j = 0; j < 8; j++) v[j] = in_s[toff[j] + base];
                float h0[4];
#pragma unroll
                for (int g = 0; g < 4; g++) h0[g] = gate_eval4(c0[g], v[g], v[g + 4]);
                float h1[2];
                h1[0] = gate_eval4(c1[0], sel4(h0, sel & 3), sel4(h0, (sel >> 4) & 3));
                h1[1] = gate_eval4(c1[1], sel4(h0, (sel >> 2) & 3), sel4(h0, (sel >> 6) & 3));
                float ha = ((sel >> 8) & 1) ? h1[1] : h1[0];
                float hb = ((sel >> 9) & 1) ? h1[1] : h1[0];
                m = fmaxf(m, gate_eval4(c2, ha, hb));
            }
        }
        int oi = f * OUTW * OUTW + (py + OUTB) * OUTW + (px + OUTB);
        if (OUTH)
            reinterpret_cast<__half*>(out_p)[oi] = __float2half(m);
        else
            reinterpret_cast<float*>(out_p)[oi] = m;
    }
    __syncthreads();
}

// ---------------------------------------------------------------------------
// FC phase (half2, 2 gates per step) with one-ahead metadata prefetch.
// ---------------------------------------------------------------------------
template <int DOUT, int GOFF>
DEV_INLINE void fc_phase_h(const __half* __restrict__ in_s, __half* __restrict__ out_s,
                           int tid) {
    constexpr int PAIRS = DOUT / 2;
    constexpr int POFF = GOFF / 2;

    int p = tid;
    uint2 ri;
    uint4 rc;
    if (p < PAIRS) {
        ri = __ldg(&g_fci2[POFF + p]);
        rc = __ldg(&g_fcc4[POFF + p]);
    }
    while (p < PAIRS) {
        int pn = p + NT;
        uint2 ri_n;
        uint4 rc_n;
        if (pn < PAIRS) {
            ri_n = __ldg(&g_fci2[POFF + pn]);
            rc_n = __ldg(&g_fcc4[POFF + pn]);
        }
        __half a0 = in_s[ri.x & 0xffffu], b0 = in_s[ri.x >> 16];
        __half a1 = in_s[ri.y & 0xffffu], b1 = in_s[ri.y >> 16];
        __half2 a01 = __halves2half2(a0, a1);
        __half2 b01 = __halves2half2(b0, b1);
        __half2 A2 = *reinterpret_cast<__half2*>(&rc.x);
        __half2 B2 = *reinterpret_cast<__half2*>(&rc.y);
        __half2 C2 = *reinterpret_cast<__half2*>(&rc.z);
        __half2 D2 = *reinterpret_cast<__half2*>(&rc.w);
        __half2 o01 = __hfma2(b01, __hfma2(a01, D2, C2), __hfma2(a01, B2, A2));
        reinterpret_cast<__half2*>(out_s)[p] = o01;
        ri = ri_n;
        rc = rc_n;
        p = pn;
    }
    __syncthreads();
}

// ---------------------------------------------------------------------------
// Kernel 2 (secondary, PDL): whole network per image in shared memory.
// ---------------------------------------------------------------------------
__global__ __launch_bounds__(NT, 1)
void mega_kernel(const float* __restrict__ x, float* __restrict__ out) {
    extern __shared__ float sm[];
    int* xbin = reinterpret_cast<int*>(sm + S_XBIN);
    int* wire = reinterpret_cast<int*>(sm + S_WIRE);
    float* lut = sm + S_LUT;
    float4* scf = reinterpret_cast<float4*>(sm + S_LUT);   // aliases LUT (dead after conv1)
    __half* act3h = reinterpret_cast<__half*>(sm + S_ACT3h);
    __half* fc1h  = reinterpret_cast<__half*>(sm + S_FC1h);
    __half* fc2h  = reinterpret_cast<__half*>(sm + S_FC2h);
    const int tid = threadIdx.x;
    const int b = blockIdx.x;

    // ---- coef-independent prologue (overlaps the coef kernel via PDL) ----
    for (int i = tid; i < 3136; i += NT) sm[S_ACT1 + i] = 0.f;
    for (int i = tid; i < 3072; i += NT) sm[S_ACT2 + i] = 0.f;
    if (tid < 784)
        xbin[tid] = (x[b * 784 + tid] > 0.5f) ? 1 : 0;

    // ---- wait for coef kernel outputs (LUT, wiring, coefs, fc metadata) ----
    cudaGridDependencySynchronize();

    for (int i = tid; i < 4096; i += NT) lut[i] = g_lut[i];
    if (tid < 128) wire[tid] = g_wire1[tid];
    __syncthreads();

    // ---- conv1 via LUT + 2x2 pool -> act1 padded (16x14x14, f32) ----
    for (int o = tid; o < 2304; o += NT) {
        int px = o % 12;
        int py = (o / 12) % 12;
        int f  = o / 144;
        int toff[8];
#pragma unroll
        for (int j = 0; j < 8; j++) toff[j] = wire[f * 8 + j];
        const float* lf = lut + f * 256;
        float m = -1e30f;
#pragma unroll
        for (int dy = 0; dy < 2; dy++) {
#pragma unroll
            for (int dx = 0; dx < 2; dx++) {
                int base = (2 * py + dy) * 28 + (2 * px + dx);
                int pat = 0;
#pragma unroll
                for (int j = 0; j < 8; j++) pat |= xbin[toff[j] + base] << j;
                m = fmaxf(m, lf[pat]);
            }
        }
        sm[S_ACT1 + f * 196 + (py + 1) * 14 + (px + 1)] = m;
    }
    __syncthreads();

    // ---- conv2: act1 (14x14 padded) -> act2 padded (48x8x8, f32) ----
    conv_phase<14, 12, 8, 1, 48, OFF_C2_0, false>(
        sm + S_ACT1, sm + S_ACT2, g_wire2, wire, scf, tid);
    // ---- conv3: act2 (8x8 padded) -> act3 (144x3x3, half) ----
    conv_phase<8, 6, 3, 0, 144, OFF_C3_0, true>(
        sm + S_ACT2, act3h, g_wire3, wire, scf, tid);

    // ---- fc stack (half2 packed, prefetch rotation) ----
    fc_phase_h<20480, FC1_OFF>(act3h, fc1h, tid);
    fc_phase_h<10240, FC2_OFF>(fc1h, fc2h, tid);
    fc_phase_h<5120, FC3_OFF>(fc2h, fc1h, tid);   // fc3 out reuses fc1 buf

    // ---- groupsum: 10 classes x 512 gates (256 half2), one warp per class ----
    const __half2* f3 = reinterpret_cast<const __half2*>(fc1h);
    int w = tid >> 5, lane = tid & 31;
    if (w < 10) {
        float s = 0.f;
#pragma unroll
        for (int k = 0; k < 8; k++) {
            float2 t = __half22float2(f3[w * 256 + lane + 32 * k]);
            s += t.x + t.y;
        }
#pragma unroll
        for (int o = 16; o; o >>= 1) s += __shfl_xor_sync(0xffffffffu, s, o);
        if (lane == 0) out[b * 10 + w] = s * (1.f / 30.f);
    }
}

// ---------------------------------------------------------------------------
static inline int cdiv(int a, int b) { return (a + b - 1) / b; }

extern "C" void kernel_launch(void* const* d_in, const int* in_sizes, int n_in,
                              void* d_out, int out_size) {
    const float* x = (const float*)d_in[0];
    const int B = in_sizes[0] / (28 * 28);

    const int* c1_i0 = (const int*)d_in[1];
    const float* c1_w0 = (const float*)d_in[2];
    const int* c1_i1 = (const int*)d_in[3];
    const float* c1_w1 = (const float*)d_in[4];
    const int* c1_i2 = (const int*)d_in[5];
    const float* c1_w2 = (const float*)d_in[6];
    const int* c2_i0 = (const int*)d_in[7];
    const float* c2_w0 = (const float*)d_in[8];
    const int* c2_i1 = (const int*)d_in[9];
    const float* c2_w1 = (const float*)d_in[10];
    const int* c2_i2 = (const int*)d_in[11];
    const float* c2_w2 = (const float*)d_in[12];
    const int* c3_i0 = (const int*)d_in[13];
    const float* c3_w0 = (const float*)d_in[14];
    const int* c3_i1 = (const int*)d_in[15];
    const float* c3_w1 = (const float*)d_in[16];
    const int* c3_i2 = (const int*)d_in[17];
    const float* c3_w2 = (const float*)d_in[18];
    const int* fc1_i = (const int*)d_in[19];
    const float* fc1_w = (const float*)d_in[20];
    const int* fc2_i = (const int*)d_in[21];
    const float* fc2_w = (const float*)d_in[22];
    const int* fc3_i = (const int*)d_in[23];
    const float* fc3_w = (const float*)d_in[24];
    float* out = (float*)d_out;

    // 1) preprocessing kernel (primary): coefs + fc metadata + LUT + wiring
    CoefArgs ca;
    ca.s[0]  = {c1_w0, c1_i0, 0, 64};
    ca.s[1]  = {c1_w1, c1_i1, 64, 32};
    ca.s[2]  = {c1_w2, c1_i2, 96, 16};
    ca.s[3]  = {c2_w0, c2_i0, OFF_C2_0, 192};
    ca.s[4]  = {c2_w1, c2_i1, 304, 96};
    ca.s[5]  = {c2_w2, c2_i2, 400, 48};
    ca.s[6]  = {c3_w0, c3_i0, OFF_C3_0, 576};
    ca.s[7]  = {c3_w1, c3_i1, 1024, 288};
    ca.s[8]  = {c3_w2, c3_i2, 1312, 144};
    ca.s[9]  = {fc1_w, fc1_i, FC1_OFF, 20480};
    ca.s[10] = {fc2_w, fc2_i, FC2_OFF, 10240};
    ca.s[11] = {fc3_w, fc3_i, FC3_OFF, 5120};
    coef_kernel<<<cdiv(N_GATES, 256), 256>>>(ca);

    // 2) mega kernel (secondary, PDL: launch overlaps primary, syncs in-kernel)
    cudaFuncSetAttribute(mega_kernel, cudaFuncAttributeMaxDynamicSharedMemorySize,
                         SMEM_BYTES);
    cudaLaunchConfig_t cfg = {};
    cfg.gridDim = dim3(B, 1, 1);
    cfg.blockDim = dim3(NT, 1, 1);
    cfg.dynamicSmemBytes = SMEM_BYTES;
    cfg.stream = 0;
    cudaLaunchAttribute attrs[1];
    attrs[0].id = cudaLaunchAttributeProgrammaticStreamSerialization;
    attrs[0].val.programmaticStreamSerializationAllowed = 1;
    cfg.attrs = attrs;
    cfg.numAttrs = 1;
    cudaLaunchKernelEx(&cfg, mega_kernel, x, out);
}